// round 7
// baseline (speedup 1.0000x reference)
#include <cuda_runtime.h>
#include <math.h>

// Problem constants
#define BB  64
#define TT  512
#define II  256
#define OO  1024
#define MM  8
#define IMD 2048

// Persistent-kernel configuration
#define NB   128            // persistent blocks (co-resident: 128 <= 148 SMs)
#define NTH  256
#define TK   32             // K-chunk
#define NCOL 3072           // 2048 rec cols + 1024 act cols
#define RECTILES 32
#define RECCH 2304          // 32 tiles * 72 chunks   (K = 2304)
#define TOTCH 2944          // + 16 tiles * 40 chunks (K = 1280)
#define CPB  23             // chunks per block (exact)
#define NSLOT 5

static_assert(NB * CPB == TOTCH, "balanced split");

// packed fp32x2 FMA (Blackwell): d = a*b + d per 32-bit lane
#define FMA2(d, a, b) asm("fma.rn.f32x2 %0, %1, %2, %0;" : "+l"(d) : "l"(a), "l"(b))

// ---------------------------------------------------------------------------
// Device state (allocation-free).  Column-major activations: [col][batch].
// ---------------------------------------------------------------------------
__device__ float g_xT[(size_t)TT * II * BB];   // x transposed: [t][i][b]
__device__ float g_WinT[(size_t)II * OO];      // W_in^T  [k][n]
__device__ float g_WhT [(size_t)OO * OO];      // W_h^T   [k][n]
__device__ float g_WirT[(size_t)II * IMD];     // W_ir^T  [k][n]
__device__ float g_WhrT[(size_t)IMD * IMD];    // W_hr^T  [k][n]
__device__ float g_xp[2][(size_t)IMD * BB];    // x_pred col-major, ping-pong
__device__ float g_hT[(size_t)OO * BB];        // hidden col-major
__device__ float g_lse[2][IMD];                // batch-axis logsumexp
__device__ float g_gate[BB * MM];
__device__ float g_part[NSLOT][(size_t)NCOL * BB]; // split-K partials [col][b]
__device__ unsigned g_arrive;
__device__ volatile unsigned g_release;

// ---------------------------------------------------------------------------
__global__ void init_kernel(const float* __restrict__ x,
                            const float* __restrict__ W_in,
                            const float* __restrict__ W_h,
                            const float* __restrict__ W_ir,
                            const float* __restrict__ W_hr) {
    size_t i = (size_t)blockIdx.x * blockDim.x + threadIdx.x;
    size_t n = (size_t)gridDim.x * blockDim.x;
    for (size_t j = i; j < (size_t)TT * II * BB; j += n) {
        size_t b = j & 63, ti = j >> 6;
        size_t ii = ti % II, tt = ti / II;
        g_xT[j] = x[(b * TT + tt) * II + ii];
    }
    for (size_t j = i; j < (size_t)II * OO; j += n) {
        size_t nn = j % OO, k = j / OO;
        g_WinT[j] = W_in[nn * II + k];
    }
    for (size_t j = i; j < (size_t)OO * OO; j += n) {
        size_t nn = j % OO, k = j / OO;
        g_WhT[j] = W_h[nn * OO + k];
    }
    for (size_t j = i; j < (size_t)II * IMD; j += n) {
        size_t nn = j % IMD, k = j / IMD;
        g_WirT[j] = W_ir[nn * II + k];
    }
    for (size_t j = i; j < (size_t)IMD * IMD; j += n) {
        size_t nn = j % IMD, k = j / IMD;
        g_WhrT[j] = W_hr[nn * IMD + k];
    }
    for (size_t j = i; j < (size_t)IMD * BB; j += n) g_xp[0][j] = 0.f;
    for (size_t j = i; j < (size_t)OO * BB;  j += n) g_hT[j] = 0.f;
    for (size_t j = i; j < IMD; j += n) g_lse[0][j] = logf((float)BB);
    if (i == 0) { g_arrive = 0u; g_release = 0u; }
}

// Grid-wide barrier (all NB blocks resident by construction)
__device__ __forceinline__ void gbar(unsigned gen) {
    __syncthreads();
    if (threadIdx.x == 0) {
        __threadfence();
        unsigned v = atomicAdd(&g_arrive, 1u);
        if (v == gen * NB + (NB - 1u)) {
            g_release = gen + 1u;
        } else {
            while (g_release <= gen) { __nanosleep(64); }
        }
    }
    __syncthreads();
}

__device__ __forceinline__ int tile_first_chunk(int tile) {
    return (tile < RECTILES) ? tile * 72 : RECCH + (tile - RECTILES) * 40;
}
__device__ __forceinline__ int tile_of(int c) {
    return (c < RECCH) ? (c / 72) : (RECTILES + (c - RECCH) / 40);
}

// chunk -> A base (row-stride 64, contiguous 2048 floats) and W^T base/ld
__device__ __forceinline__ void chunk_ptrs(int c, int t, int cur,
                                           const float*& Ap, const float*& Wp,
                                           size_t& ldw, bool& cg) {
    bool rec; int tloc, kc;
    if (c < RECCH) { rec = true;  tloc = c / 72;           kc = c - tloc * 72; }
    else           { rec = false; tloc = (c - RECCH) / 40; kc = (c - RECCH) - tloc * 40; }
    const int n0 = tloc * 64;
    const int k0 = kc * TK;
    if (k0 < II) {
        Ap = g_xT + ((size_t)t * II + k0) * BB;
        if (rec) { Wp = g_WirT + (size_t)k0 * IMD + n0; ldw = IMD; }
        else     { Wp = g_WinT + (size_t)k0 * OO  + n0; ldw = OO;  }
        cg = false;
    } else {
        const int kk = k0 - II;
        if (rec) { Ap = g_xp[cur] + (size_t)kk * BB;
                   Wp = g_WhrT + (size_t)kk * IMD + n0; ldw = IMD; }
        else     { Ap = g_hT + (size_t)kk * BB;
                   Wp = g_WhT + (size_t)kk * OO + n0;  ldw = OO; }
        cg = true;
    }
}

// ---------------------------------------------------------------------------
// Whole scan, one kernel. Per step: P1 GEMM(+gate) | bar | P2 reduce+act+LSE | bar
// ---------------------------------------------------------------------------
__global__ void __launch_bounds__(NTH) rnn_persistent(
    const float* __restrict__ x,
    const float* __restrict__ b_in, const float* __restrict__ b_ir,
    const float* __restrict__ periods, const float* __restrict__ shifts,
    float* __restrict__ ys, float* __restrict__ hfin, float* __restrict__ ps)
{
    __shared__ float AsB[2][TK * 64];    // k-major A tiles   [k][64]
    __shared__ float WsB[2][TK * 128];   // duplicated W tiles [k][2n]
    float* red = &AsB[0][0];             // scratch alias (P1b / P2 reductions)

    const int tid = threadIdx.x;
    const int bid = blockIdx.x;
    const int b0  = (tid & 7) * 8;            // 8 consecutive batches
    const int o0  = ((tid >> 3) & 31) * 2;    // 2 consecutive outputs
    const int wrow = tid >> 4;                // W loader row (0..15)
    const int wcg  = tid & 15;                // W loader col group

    unsigned gen = 0;
    for (int t = 0; t < TT; t++) {
        const int cur = t & 1, nxt = cur ^ 1;

        // ================= P1: split-K GEMM =================
        const int c0 = bid * CPB, c1 = c0 + CPB;
        unsigned long long acc[2][4];
        int cur_tile = -1;
        float4 av0, av1, wv0, wv1;

        {   // preload chunk c0
            const float *Ap, *Wp; size_t ldw; bool cg;
            chunk_ptrs(c0, t, cur, Ap, Wp, ldw, cg);
            const float4* A4 = (const float4*)Ap;
            if (cg) { av0 = __ldcg(A4 + tid); av1 = __ldcg(A4 + tid + 256); }
            else    { av0 = A4[tid];          av1 = A4[tid + 256]; }
            wv0 = *(const float4*)(Wp + (size_t)wrow * ldw + wcg * 4);
            wv1 = *(const float4*)(Wp + (size_t)(wrow + 16) * ldw + wcg * 4);
        }
        {   // store chunk c0 -> buffer 0
            ((float4*)AsB[0])[tid] = av0;
            ((float4*)AsB[0])[tid + 256] = av1;
            float4 d;
            d = make_float4(wv0.x, wv0.x, wv0.y, wv0.y);
            *(float4*)&WsB[0][wrow * 128 + wcg * 8] = d;
            d = make_float4(wv0.z, wv0.z, wv0.w, wv0.w);
            *(float4*)&WsB[0][wrow * 128 + wcg * 8 + 4] = d;
            d = make_float4(wv1.x, wv1.x, wv1.y, wv1.y);
            *(float4*)&WsB[0][(wrow + 16) * 128 + wcg * 8] = d;
            d = make_float4(wv1.z, wv1.z, wv1.w, wv1.w);
            *(float4*)&WsB[0][(wrow + 16) * 128 + wcg * 8 + 4] = d;
        }

        int p = 0;
        for (int c = c0; c < c1; ++c) {
            const int gtile = tile_of(c);
            if (gtile != cur_tile) {
                if (cur_tile >= 0) {   // flush old tile's partials
                    const int fc = tile_first_chunk(cur_tile);
                    float* base = g_part[bid - fc / CPB]
                                + ((size_t)cur_tile * 64 + o0) * BB + b0;
                    ulonglong2 v;
                    v.x = acc[0][0]; v.y = acc[0][1]; *(ulonglong2*)base = v;
                    v.x = acc[0][2]; v.y = acc[0][3]; *((ulonglong2*)base + 1) = v;
                    float* base1 = base + BB;
                    v.x = acc[1][0]; v.y = acc[1][1]; *(ulonglong2*)base1 = v;
                    v.x = acc[1][2]; v.y = acc[1][3]; *((ulonglong2*)base1 + 1) = v;
                }
                acc[0][0] = acc[0][1] = acc[0][2] = acc[0][3] = 0ull;
                acc[1][0] = acc[1][1] = acc[1][2] = acc[1][3] = 0ull;
                cur_tile = gtile;
            }

            __syncthreads();   // buf p stores visible; prior reads of p^1 done

            if (c + 1 < c1) {  // prefetch next chunk into regs
                const float *Ap, *Wp; size_t ldw; bool cg;
                chunk_ptrs(c + 1, t, cur, Ap, Wp, ldw, cg);
                const float4* A4 = (const float4*)Ap;
                if (cg) { av0 = __ldcg(A4 + tid); av1 = __ldcg(A4 + tid + 256); }
                else    { av0 = A4[tid];          av1 = A4[tid + 256]; }
                wv0 = *(const float4*)(Wp + (size_t)wrow * ldw + wcg * 4);
                wv1 = *(const float4*)(Wp + (size_t)(wrow + 16) * ldw + wcg * 4);
            }

            // compute on buffer p
            {
                const float* Ar = AsB[p];
                const float* Wr = WsB[p];
                #pragma unroll 8
                for (int k = 0; k < TK; ++k) {
                    ulonglong2 a01 = *(const ulonglong2*)(Ar + k * 64 + b0);
                    ulonglong2 a23 = *(const ulonglong2*)(Ar + k * 64 + b0 + 4);
                    ulonglong2 ww  = *(const ulonglong2*)(Wr + k * 128 + o0 * 2);
                    FMA2(acc[0][0], a01.x, ww.x); FMA2(acc[0][1], a01.y, ww.x);
                    FMA2(acc[0][2], a23.x, ww.x); FMA2(acc[0][3], a23.y, ww.x);
                    FMA2(acc[1][0], a01.x, ww.y); FMA2(acc[1][1], a01.y, ww.y);
                    FMA2(acc[1][2], a23.x, ww.y); FMA2(acc[1][3], a23.y, ww.y);
                }
            }

            if (c + 1 < c1) {  // store prefetched chunk -> buffer p^1
                const int q = p ^ 1;
                ((float4*)AsB[q])[tid] = av0;
                ((float4*)AsB[q])[tid + 256] = av1;
                float4 d;
                d = make_float4(wv0.x, wv0.x, wv0.y, wv0.y);
                *(float4*)&WsB[q][wrow * 128 + wcg * 8] = d;
                d = make_float4(wv0.z, wv0.z, wv0.w, wv0.w);
                *(float4*)&WsB[q][wrow * 128 + wcg * 8 + 4] = d;
                d = make_float4(wv1.x, wv1.x, wv1.y, wv1.y);
                *(float4*)&WsB[q][(wrow + 16) * 128 + wcg * 8] = d;
                d = make_float4(wv1.z, wv1.z, wv1.w, wv1.w);
                *(float4*)&WsB[q][(wrow + 16) * 128 + wcg * 8 + 4] = d;
            }
            p ^= 1;
        }
        {   // final flush
            const int fc = tile_first_chunk(cur_tile);
            float* base = g_part[bid - fc / CPB]
                        + ((size_t)cur_tile * 64 + o0) * BB + b0;
            ulonglong2 v;
            v.x = acc[0][0]; v.y = acc[0][1]; *(ulonglong2*)base = v;
            v.x = acc[0][2]; v.y = acc[0][3]; *((ulonglong2*)base + 1) = v;
            float* base1 = base + BB;
            v.x = acc[1][0]; v.y = acc[1][1]; *(ulonglong2*)base1 = v;
            v.x = acc[1][2]; v.y = acc[1][3]; *((ulonglong2*)base1 + 1) = v;
        }

        // ---- P1b: surprisal dot -> gate (previous step's xp & lse) ----
        for (int d = bid; d < BB * MM; d += NB) {
            const int b = d >> 3, m = d & 7;
            float xv  = x[((size_t)b * TT + t) * II + tid];
            float xpv = __ldcg(&g_xp[cur][(size_t)(m * II + tid) * BB + b]);
            float lsv = __ldcg(&g_lse[cur][m * II + tid]);
            float part = (xpv - lsv) * xv;
            #pragma unroll
            for (int off = 16; off; off >>= 1)
                part += __shfl_xor_sync(0xffffffffu, part, off);
            __syncthreads();
            if ((tid & 31) == 0) red[tid >> 5] = part;
            __syncthreads();
            if (tid == 0) {
                float tot = 0.f;
                #pragma unroll
                for (int w = 0; w < 8; w++) tot += red[w];
                float mp = tot * (1.0f / II) * periods[m];
                float gate = (sinf((float)t * mp + shifts[m]) + 1.f) * 0.5f;
                g_gate[d] = gate;
                ps[((size_t)b * TT + t) * MM + m] = mp;
            }
        }

        gbar(gen++);

        // ============ P2: reduce + activate + blend + fused LSE ============
        {
            float* redm = &AsB[0][0];
            float* reds = &AsB[0][8];
            const int c0p = bid * 24;
            const int bb  = tid & 63;
            const int clq = tid >> 6;
            const int w   = tid >> 5;
            #pragma unroll
            for (int pass = 0; pass < 6; ++pass) {
                const int col  = c0p + pass * 4 + clq;
                const int tile = col >> 6;
                const int fc    = tile_first_chunk(tile);
                const int lastc = fc + ((tile < RECTILES) ? 71 : 39);
                const int ns    = lastc / CPB - fc / CPB;
                float s = 0.f;
                for (int sl = 0; sl <= ns; ++sl)
                    s += __ldcg(&g_part[sl][(size_t)col * BB + bb]);
                const bool isrec = col < IMD;
                float v = 0.f;
                if (isrec) {
                    v = tanhf(s + b_ir[col]);
                    g_xp[nxt][(size_t)col * BB + bb] = v;
                } else {
                    const int o = col - IMD;
                    float a  = tanhf(s + b_in[o]);
                    float gt = __ldcg(&g_gate[bb * MM + (o >> 7)]);
                    float hv = g_hT[(size_t)o * BB + bb];
                    float y  = (1.f - gt) * a + gt * hv;
                    g_hT[(size_t)o * BB + bb] = y;
                    ys[((size_t)bb * TT + t) * OO + o] = y;
                }
                // column LSE over 64 batches (2 warps); act cols produce junk, unused
                float mx = v;
                #pragma unroll
                for (int off = 16; off; off >>= 1)
                    mx = fmaxf(mx, __shfl_xor_sync(0xffffffffu, mx, off));
                float se = isrec ? expf(v - mx) : 0.f;
                #pragma unroll
                for (int off = 16; off; off >>= 1)
                    se += __shfl_xor_sync(0xffffffffu, se, off);
                __syncthreads();
                if ((tid & 31) == 0) { redm[w] = mx; reds[w] = se; }
                __syncthreads();
                if (isrec && (tid & 63) == 0) {
                    float m0 = redm[w], m1 = redm[w + 1];
                    float M = fmaxf(m0, m1);
                    float S = reds[w] * expf(m0 - M) + reds[w + 1] * expf(m1 - M);
                    g_lse[nxt][col] = M + logf(S);
                }
            }
        }

        gbar(gen++);
    }

    // h_final: col-major -> [B][O]
    for (int idx = bid * NTH + tid; idx < BB * OO; idx += NB * NTH) {
        int o = idx >> 6, b = idx & 63;
        hfin[(size_t)b * OO + o] = __ldcg(&g_hT[idx]);
    }
}

// ---------------------------------------------------------------------------
// 2 graph nodes. Inputs: x, W_in, b_in, W_h, W_ir, b_ir, W_hr, periods, shifts
// Output: concat(ys [B,T,O], h_final [B,O], ps [B,T,M]) fp32
// ---------------------------------------------------------------------------
extern "C" void kernel_launch(void* const* d_in, const int* in_sizes, int n_in,
                              void* d_out, int out_size) {
    const float* x       = (const float*)d_in[0];
    const float* W_in    = (const float*)d_in[1];
    const float* b_in    = (const float*)d_in[2];
    const float* W_h     = (const float*)d_in[3];
    const float* W_ir    = (const float*)d_in[4];
    const float* b_ir    = (const float*)d_in[5];
    const float* W_hr    = (const float*)d_in[6];
    const float* periods = (const float*)d_in[7];
    const float* shifts  = (const float*)d_in[8];

    float* out  = (float*)d_out;
    float* ys   = out;                                  // [B,T,O]
    float* hfin = out + (size_t)BB * TT * OO;           // [B,O]
    float* ps   = hfin + (size_t)BB * OO;               // [B,T,M]

    init_kernel<<<1024, 256>>>(x, W_in, W_h, W_ir, W_hr);
    rnn_persistent<<<NB, NTH>>>(x, b_in, b_ir, periods, shifts, ys, hfin, ps);
}

// round 8
// speedup vs baseline: 1.8112x; 1.8112x over previous
#include <cuda_runtime.h>
#include <math.h>

// Problem constants
#define BB  64
#define TT  512
#define II  256
#define OO  1024
#define MM  8
#define IMD 2048

// Persistent-kernel configuration
#define NB   128            // persistent blocks (co-resident: 128 <= 148 SMs)
#define NTH  256
#define TK   32             // K-chunk
#define NCOL 3072           // 2048 rec cols + 1024 act cols
#define RECTILES 32
#define RECCH 2304          // 32 tiles * 72 chunks   (K = 2304)
#define TOTCH 2944          // + 16 tiles * 40 chunks (K = 1280)
#define CPB  23             // chunks per block (exact)
#define NSLOT 5

static_assert(NB * CPB == TOTCH, "balanced split");

// ---------------------------------------------------------------------------
// Device state (allocation-free).  Column-major activations: [col][batch].
// ---------------------------------------------------------------------------
__device__ float g_xT[(size_t)TT * II * BB];   // x transposed: [t][i][b]
__device__ float g_WinT[(size_t)II * OO];      // W_in^T  [k][n]
__device__ float g_WhT [(size_t)OO * OO];      // W_h^T   [k][n]
__device__ float g_WirT[(size_t)II * IMD];     // W_ir^T  [k][n]
__device__ float g_WhrT[(size_t)IMD * IMD];    // W_hr^T  [k][n]
__device__ float g_xp[2][(size_t)IMD * BB];    // x_pred col-major, ping-pong
__device__ float g_hT[(size_t)OO * BB];        // hidden col-major
__device__ float g_lse[2][IMD];                // batch-axis logsumexp
__device__ float g_gate[BB * MM];
__device__ float g_part[NSLOT][(size_t)NCOL * BB]; // split-K partials [col][b]
__device__ unsigned g_arrive;
__device__ volatile unsigned g_release;

// ---------------------------------------------------------------------------
__global__ void init_kernel(const float* __restrict__ x,
                            const float* __restrict__ W_in,
                            const float* __restrict__ W_h,
                            const float* __restrict__ W_ir,
                            const float* __restrict__ W_hr) {
    size_t i = (size_t)blockIdx.x * blockDim.x + threadIdx.x;
    size_t n = (size_t)gridDim.x * blockDim.x;
    for (size_t j = i; j < (size_t)TT * II * BB; j += n) {
        size_t b = j & 63, ti = j >> 6;
        size_t ii = ti % II, tt = ti / II;
        g_xT[j] = x[(b * TT + tt) * II + ii];
    }
    for (size_t j = i; j < (size_t)II * OO; j += n) {
        size_t nn = j % OO, k = j / OO;
        g_WinT[j] = W_in[nn * II + k];
    }
    for (size_t j = i; j < (size_t)OO * OO; j += n) {
        size_t nn = j % OO, k = j / OO;
        g_WhT[j] = W_h[nn * OO + k];
    }
    for (size_t j = i; j < (size_t)II * IMD; j += n) {
        size_t nn = j % IMD, k = j / IMD;
        g_WirT[j] = W_ir[nn * II + k];
    }
    for (size_t j = i; j < (size_t)IMD * IMD; j += n) {
        size_t nn = j % IMD, k = j / IMD;
        g_WhrT[j] = W_hr[nn * IMD + k];
    }
    for (size_t j = i; j < (size_t)IMD * BB; j += n) g_xp[0][j] = 0.f;
    for (size_t j = i; j < (size_t)OO * BB;  j += n) g_hT[j] = 0.f;
    for (size_t j = i; j < IMD; j += n) g_lse[0][j] = logf((float)BB);
    if (i == 0) { g_arrive = 0u; g_release = 0u; }
}

// Grid-wide barrier (all NB blocks resident by construction)
__device__ __forceinline__ void gbar(unsigned gen) {
    __syncthreads();
    if (threadIdx.x == 0) {
        __threadfence();
        unsigned v = atomicAdd(&g_arrive, 1u);
        if (v == gen * NB + (NB - 1u)) {
            g_release = gen + 1u;
        } else {
            while (g_release <= gen) { __nanosleep(64); }
        }
    }
    __syncthreads();
}

__device__ __forceinline__ int tile_first_chunk(int tile) {
    return (tile < RECTILES) ? tile * 72 : RECCH + (tile - RECTILES) * 40;
}
__device__ __forceinline__ int tile_of(int c) {
    return (c < RECCH) ? (c / 72) : (RECTILES + (c - RECCH) / 40);
}

// chunk -> A base (contiguous [k][64], 2048 floats) and W^T base/ld
__device__ __forceinline__ void chunk_ptrs(int c, int t, int cur,
                                           const float*& Ap, const float*& Wp,
                                           size_t& ldw, bool& cg) {
    bool rec; int tloc, kc;
    if (c < RECCH) { rec = true;  tloc = c / 72;           kc = c - tloc * 72; }
    else           { rec = false; tloc = (c - RECCH) / 40; kc = (c - RECCH) - tloc * 40; }
    const int n0 = tloc * 64;
    const int k0 = kc * TK;
    if (k0 < II) {
        Ap = g_xT + ((size_t)t * II + k0) * BB;
        if (rec) { Wp = g_WirT + (size_t)k0 * IMD + n0; ldw = IMD; }
        else     { Wp = g_WinT + (size_t)k0 * OO  + n0; ldw = OO;  }
        cg = false;
    } else {
        const int kk = k0 - II;
        if (rec) { Ap = g_xp[cur] + (size_t)kk * BB;
                   Wp = g_WhrT + (size_t)kk * IMD + n0; ldw = IMD; }
        else     { Ap = g_hT + (size_t)kk * BB;
                   Wp = g_WhT + (size_t)kk * OO + n0;  ldw = OO; }
        cg = true;
    }
}

// ---------------------------------------------------------------------------
// Whole scan, one kernel. Per step: P1 GEMM(+gate) | bar | P2 reduce+act+LSE | bar
// ---------------------------------------------------------------------------
__global__ void __launch_bounds__(NTH) rnn_persistent(
    const float* __restrict__ x,
    const float* __restrict__ b_in, const float* __restrict__ b_ir,
    const float* __restrict__ periods, const float* __restrict__ shifts,
    float* __restrict__ ys, float* __restrict__ hfin, float* __restrict__ ps)
{
    __shared__ float AsB[2][TK * 64];    // k-major A tiles [k][64 b]
    __shared__ float WsB[2][TK * 64];    // k-major W tiles [k][64 n]
    float* red = &AsB[0][0];             // scratch alias (P1b / P2 reductions)

    const int tid = threadIdx.x;
    const int bid = blockIdx.x;
    const int b0  = (tid & 15) * 4;      // 4 consecutive batches
    const int o0  = (tid >> 4) * 4;      // 4 consecutive outputs
    const int wk  = tid >> 4;            // W loader row (0..15)
    const int wu  = (tid & 15) * 4;      // W loader float offset in row

    unsigned gen = 0;
    for (int t = 0; t < TT; t++) {
        const int cur = t & 1, nxt = cur ^ 1;

        // ================= P1: split-K GEMM =================
        const int c0 = bid * CPB, c1 = c0 + CPB;
        float4 acc[4];                   // acc[j] = 4 batches for output o0+j
        int cur_tile = -1;
        float4 av0, av1, wv0, wv1;

        {   // preload chunk c0
            const float *Ap, *Wp; size_t ldw; bool cg;
            chunk_ptrs(c0, t, cur, Ap, Wp, ldw, cg);
            const float4* A4 = (const float4*)Ap;
            if (cg) { av0 = __ldcg(A4 + tid); av1 = __ldcg(A4 + tid + 256); }
            else    { av0 = A4[tid];          av1 = A4[tid + 256]; }
            wv0 = *(const float4*)(Wp + (size_t)wk * ldw + wu);
            wv1 = *(const float4*)(Wp + (size_t)(wk + 16) * ldw + wu);
        }
        {   // store chunk c0 -> buffer 0 (straight float4 copies)
            ((float4*)AsB[0])[tid] = av0;
            ((float4*)AsB[0])[tid + 256] = av1;
            *(float4*)&WsB[0][wk * 64 + wu] = wv0;
            *(float4*)&WsB[0][(wk + 16) * 64 + wu] = wv1;
        }

        int p = 0;
        for (int c = c0; c < c1; ++c) {
            const int gtile = tile_of(c);
            if (gtile != cur_tile) {
                if (cur_tile >= 0) {   // flush old tile's partials (coalesced)
                    const int fc = tile_first_chunk(cur_tile);
                    float* base = g_part[bid - fc / CPB]
                                + ((size_t)cur_tile * 64 + o0) * BB + b0;
                    #pragma unroll
                    for (int j = 0; j < 4; j++)
                        *(float4*)(base + j * BB) = acc[j];
                }
                #pragma unroll
                for (int j = 0; j < 4; j++)
                    acc[j] = make_float4(0.f, 0.f, 0.f, 0.f);
                cur_tile = gtile;
            }

            __syncthreads();   // buf p stores visible; prior reads of p^1 done

            if (c + 1 < c1) {  // prefetch next chunk into regs
                const float *Ap, *Wp; size_t ldw; bool cg;
                chunk_ptrs(c + 1, t, cur, Ap, Wp, ldw, cg);
                const float4* A4 = (const float4*)Ap;
                if (cg) { av0 = __ldcg(A4 + tid); av1 = __ldcg(A4 + tid + 256); }
                else    { av0 = A4[tid];          av1 = A4[tid + 256]; }
                wv0 = *(const float4*)(Wp + (size_t)wk * ldw + wu);
                wv1 = *(const float4*)(Wp + (size_t)(wk + 16) * ldw + wu);
            }

            // compute on buffer p: per k, 2 LDS.128 + 16 FFMA
            {
                const float* Ar = AsB[p];
                const float* Wr = WsB[p];
                #pragma unroll 8
                for (int k = 0; k < TK; ++k) {
                    float4 a = *(const float4*)(Ar + k * 64 + b0);
                    float4 w = *(const float4*)(Wr + k * 64 + o0);
                    acc[0].x += a.x * w.x; acc[0].y += a.y * w.x;
                    acc[0].z += a.z * w.x; acc[0].w += a.w * w.x;
                    acc[1].x += a.x * w.y; acc[1].y += a.y * w.y;
                    acc[1].z += a.z * w.y; acc[1].w += a.w * w.y;
                    acc[2].x += a.x * w.z; acc[2].y += a.y * w.z;
                    acc[2].z += a.z * w.z; acc[2].w += a.w * w.z;
                    acc[3].x += a.x * w.w; acc[3].y += a.y * w.w;
                    acc[3].z += a.z * w.w; acc[3].w += a.w * w.w;
                }
            }

            if (c + 1 < c1) {  // store prefetched chunk -> buffer p^1
                const int q = p ^ 1;
                ((float4*)AsB[q])[tid] = av0;
                ((float4*)AsB[q])[tid + 256] = av1;
                *(float4*)&WsB[q][wk * 64 + wu] = wv0;
                *(float4*)&WsB[q][(wk + 16) * 64 + wu] = wv1;
            }
            p ^= 1;
        }
        {   // final flush
            const int fc = tile_first_chunk(cur_tile);
            float* base = g_part[bid - fc / CPB]
                        + ((size_t)cur_tile * 64 + o0) * BB + b0;
            #pragma unroll
            for (int j = 0; j < 4; j++)
                *(float4*)(base + j * BB) = acc[j];
        }

        // ---- P1b: surprisal dot -> gate (previous step's xp & lse) ----
        for (int d = bid; d < BB * MM; d += NB) {
            const int b = d >> 3, m = d & 7;
            float xv  = x[((size_t)b * TT + t) * II + tid];
            float xpv = __ldcg(&g_xp[cur][(size_t)(m * II + tid) * BB + b]);
            float lsv = __ldcg(&g_lse[cur][m * II + tid]);
            float part = (xpv - lsv) * xv;
            #pragma unroll
            for (int off = 16; off; off >>= 1)
                part += __shfl_xor_sync(0xffffffffu, part, off);
            __syncthreads();
            if ((tid & 31) == 0) red[tid >> 5] = part;
            __syncthreads();
            if (tid == 0) {
                float tot = 0.f;
                #pragma unroll
                for (int w = 0; w < 8; w++) tot += red[w];
                float mp = tot * (1.0f / II) * periods[m];
                float gate = (sinf((float)t * mp + shifts[m]) + 1.f) * 0.5f;
                g_gate[d] = gate;
                ps[((size_t)b * TT + t) * MM + m] = mp;
            }
        }

        gbar(gen++);

        // ============ P2: reduce + activate + blend + fused LSE ============
        {
            float* redm = &AsB[0][0];
            float* reds = &AsB[0][8];
            const int c0p = bid * 24;
            const int bb  = tid & 63;
            const int clq = tid >> 6;
            const int w   = tid >> 5;
            #pragma unroll
            for (int pass = 0; pass < 6; ++pass) {
                const int col  = c0p + pass * 4 + clq;
                const int tile = col >> 6;
                const int fc    = tile_first_chunk(tile);
                const int lastc = fc + ((tile < RECTILES) ? 71 : 39);
                const int ns    = lastc / CPB - fc / CPB;
                float s = 0.f;
                for (int sl = 0; sl <= ns; ++sl)
                    s += __ldcg(&g_part[sl][(size_t)col * BB + bb]);
                const bool isrec = col < IMD;
                float v = 0.f;
                if (isrec) {
                    v = tanhf(s + b_ir[col]);
                    g_xp[nxt][(size_t)col * BB + bb] = v;
                } else {
                    const int o = col - IMD;
                    float a  = tanhf(s + b_in[o]);
                    float gt = __ldcg(&g_gate[bb * MM + (o >> 7)]);
                    float hv = g_hT[(size_t)o * BB + bb];
                    float y  = (1.f - gt) * a + gt * hv;
                    g_hT[(size_t)o * BB + bb] = y;
                    ys[((size_t)bb * TT + t) * OO + o] = y;
                }
                // column LSE over 64 batches (2 warps); act cols produce junk, unused
                float mx = v;
                #pragma unroll
                for (int off = 16; off; off >>= 1)
                    mx = fmaxf(mx, __shfl_xor_sync(0xffffffffu, mx, off));
                float se = isrec ? expf(v - mx) : 0.f;
                #pragma unroll
                for (int off = 16; off; off >>= 1)
                    se += __shfl_xor_sync(0xffffffffu, se, off);
                __syncthreads();
                if ((tid & 31) == 0) { redm[w] = mx; reds[w] = se; }
                __syncthreads();
                if (isrec && (tid & 63) == 0) {
                    float m0 = redm[w], m1 = redm[w + 1];
                    float M = fmaxf(m0, m1);
                    float S = reds[w] * expf(m0 - M) + reds[w + 1] * expf(m1 - M);
                    g_lse[nxt][col] = M + logf(S);
                }
            }
        }

        gbar(gen++);
    }

    // h_final: col-major -> [B][O]
    for (int idx = bid * NTH + tid; idx < BB * OO; idx += NB * NTH) {
        int o = idx >> 6, b = idx & 63;
        hfin[(size_t)b * OO + o] = __ldcg(&g_hT[idx]);
    }
}

// ---------------------------------------------------------------------------
// 2 graph nodes. Inputs: x, W_in, b_in, W_h, W_ir, b_ir, W_hr, periods, shifts
// Output: concat(ys [B,T,O], h_final [B,O], ps [B,T,M]) fp32
// ---------------------------------------------------------------------------
extern "C" void kernel_launch(void* const* d_in, const int* in_sizes, int n_in,
                              void* d_out, int out_size) {
    const float* x       = (const float*)d_in[0];
    const float* W_in    = (const float*)d_in[1];
    const float* b_in    = (const float*)d_in[2];
    const float* W_h     = (const float*)d_in[3];
    const float* W_ir    = (const float*)d_in[4];
    const float* b_ir    = (const float*)d_in[5];
    const float* W_hr    = (const float*)d_in[6];
    const float* periods = (const float*)d_in[7];
    const float* shifts  = (const float*)d_in[8];

    float* out  = (float*)d_out;
    float* ys   = out;                                  // [B,T,O]
    float* hfin = out + (size_t)BB * TT * OO;           // [B,O]
    float* ps   = hfin + (size_t)BB * OO;               // [B,T,M]

    init_kernel<<<1024, 256>>>(x, W_in, W_h, W_ir, W_hr);
    rnn_persistent<<<NB, NTH>>>(x, b_in, b_ir, periods, shifts, ys, hfin, ps);
}

// round 10
// speedup vs baseline: 1.9366x; 1.0693x over previous
#include <cuda_runtime.h>
#include <math.h>

// Problem constants
#define BB  64
#define TT  512
#define II  256
#define OO  1024
#define MM  8
#define IMD 2048

// Persistent-kernel configuration
#define NB   128            // persistent blocks (co-resident: 128 <= SM count)
#define NTH  512
#define TK   16             // K-chunk depth
#define TILEN 128           // output-cols per tile
#define NCOL 3072           // 2048 rec cols + 1024 act cols
#define RECTILES 16         // rec: 2048/128
#define RECCPT 144          // chunks per rec tile  (K = 2304, TK=16)
#define ACTCPT 80           // chunks per act tile  (K = 1280, TK=16)
#define RECCH  2304         // 16 * 144
#define TOTCH  2944         // + 8 * 80
#define CPB  23             // chunks per block (exact: 2944/128)
#define NSLOT 8             // max split-K owners per tile (ceil(143/23)+1)

static_assert(NB * CPB == TOTCH, "balanced split");

// ---------------------------------------------------------------------------
// Device state (allocation-free).  Column-major activations: [col][batch].
// ---------------------------------------------------------------------------
__device__ float g_xT[(size_t)TT * II * BB];   // x transposed: [t][i][b]
__device__ float g_WinT[(size_t)II * OO];      // W_in^T  [k][n]
__device__ float g_WhT [(size_t)OO * OO];      // W_h^T   [k][n]
__device__ float g_WirT[(size_t)II * IMD];     // W_ir^T  [k][n]
__device__ float g_WhrT[(size_t)IMD * IMD];    // W_hr^T  [k][n]
__device__ float g_xp[2][(size_t)IMD * BB];    // x_pred col-major, ping-pong
__device__ float g_hT[(size_t)OO * BB];        // hidden col-major
__device__ float g_lse[2][IMD];                // batch-axis logsumexp
__device__ float g_gate[BB * MM];
__device__ float g_part[NSLOT][(size_t)NCOL * BB]; // split-K partials [col][b]
__device__ unsigned g_arrive;
__device__ volatile unsigned g_release;

// ---------------------------------------------------------------------------
__global__ void init_kernel(const float* __restrict__ x,
                            const float* __restrict__ W_in,
                            const float* __restrict__ W_h,
                            const float* __restrict__ W_ir,
                            const float* __restrict__ W_hr) {
    size_t i = (size_t)blockIdx.x * blockDim.x + threadIdx.x;
    size_t n = (size_t)gridDim.x * blockDim.x;
    for (size_t j = i; j < (size_t)TT * II * BB; j += n) {
        size_t b = j & 63, ti = j >> 6;
        size_t ii = ti % II, tt = ti / II;
        g_xT[j] = x[(b * TT + tt) * II + ii];
    }
    for (size_t j = i; j < (size_t)II * OO; j += n) {
        size_t nn = j % OO, k = j / OO;
        g_WinT[j] = W_in[nn * II + k];
    }
    for (size_t j = i; j < (size_t)OO * OO; j += n) {
        size_t nn = j % OO, k = j / OO;
        g_WhT[j] = W_h[nn * OO + k];
    }
    for (size_t j = i; j < (size_t)II * IMD; j += n) {
        size_t nn = j % IMD, k = j / IMD;
        g_WirT[j] = W_ir[nn * II + k];
    }
    for (size_t j = i; j < (size_t)IMD * IMD; j += n) {
        size_t nn = j % IMD, k = j / IMD;
        g_WhrT[j] = W_hr[nn * IMD + k];
    }
    for (size_t j = i; j < (size_t)IMD * BB; j += n) g_xp[0][j] = 0.f;
    for (size_t j = i; j < (size_t)OO * BB;  j += n) g_hT[j] = 0.f;
    for (size_t j = i; j < IMD; j += n) g_lse[0][j] = logf((float)BB);
    if (i == 0) { g_arrive = 0u; g_release = 0u; }
}

// Grid-wide barrier (all NB blocks resident by construction)
__device__ __forceinline__ void gbar(unsigned gen) {
    __syncthreads();
    if (threadIdx.x == 0) {
        __threadfence();
        unsigned v = atomicAdd(&g_arrive, 1u);
        if (v == gen * NB + (NB - 1u)) {
            g_release = gen + 1u;
        } else {
            while (g_release <= gen) { __nanosleep(64); }
        }
    }
    __syncthreads();
}

__device__ __forceinline__ int tile_first_chunk(int tile) {
    return (tile < RECTILES) ? tile * RECCPT : RECCH + (tile - RECTILES) * ACTCPT;
}
__device__ __forceinline__ int tile_of(int c) {
    return (c < RECCH) ? (c / RECCPT) : (RECTILES + (c - RECCH) / ACTCPT);
}

// chunk -> A base (contiguous [k][64], 1024 floats) and W^T base/ld
__device__ __forceinline__ void chunk_ptrs(int c, int t, int cur,
                                           const float*& Ap, const float*& Wp,
                                           size_t& ldw, bool& cg) {
    bool rec; int tloc, kc;
    if (c < RECCH) { rec = true;  tloc = c / RECCPT; kc = c - tloc * RECCPT; }
    else { rec = false; tloc = (c - RECCH) / ACTCPT; kc = (c - RECCH) - tloc * ACTCPT; }
    const int n0 = tloc * TILEN;
    const int k0 = kc * TK;
    if (k0 < II) {
        Ap = g_xT + ((size_t)t * II + k0) * BB;
        if (rec) { Wp = g_WirT + (size_t)k0 * IMD + n0; ldw = IMD; }
        else     { Wp = g_WinT + (size_t)k0 * OO  + n0; ldw = OO;  }
        cg = false;
    } else {
        const int kk = k0 - II;
        if (rec) { Ap = g_xp[cur] + (size_t)kk * BB;
                   Wp = g_WhrT + (size_t)kk * IMD + n0; ldw = IMD; }
        else     { Ap = g_hT + (size_t)kk * BB;
                   Wp = g_WhT + (size_t)kk * OO + n0;  ldw = OO; }
        cg = true;
    }
}

// ---------------------------------------------------------------------------
// Whole scan, one kernel. Per step: P1 GEMM(+gate) | bar | P2 reduce+act+LSE | bar
// ---------------------------------------------------------------------------
__global__ void __launch_bounds__(NTH) rnn_persistent(
    const float* __restrict__ x,
    const float* __restrict__ b_in, const float* __restrict__ b_ir,
    const float* __restrict__ periods, const float* __restrict__ shifts,
    float* __restrict__ ys, float* __restrict__ hfin, float* __restrict__ ps)
{
    __shared__ float AsB[2][TK * 64];        // k-major A tiles [k][64 b]
    __shared__ float WsB[2][TK * TILEN];     // k-major W tiles [k][128 n]
    float* red = &AsB[0][0];                 // scratch alias (reductions)

    const int tid = threadIdx.x;
    const int bid = blockIdx.x;
    const int b0  = (tid & 15) * 4;          // 4 consecutive batches
    const int o0  = (tid >> 4) * 4;          // 4 consecutive outputs (0..124)
    const int wkr = tid >> 5;                // W loader row (0..15)
    const int wku = (tid & 31) * 4;          // W loader float offset (0..124)

    unsigned gen = 0;
    for (int t = 0; t < TT; t++) {
        const int cur = t & 1, nxt = cur ^ 1;

        // ================= P1: split-K GEMM =================
        const int c0 = bid * CPB, c1 = c0 + CPB;
        float4 acc[4];                       // acc[j] = 4 batches @ output o0+j
        int cur_tile = -1;
        float4 av, wv;

        {   // preload chunk c0
            const float *Ap, *Wp; size_t ldw; bool cg;
            chunk_ptrs(c0, t, cur, Ap, Wp, ldw, cg);
            if (tid < 256) {
                const float4* A4 = (const float4*)Ap;
                av = cg ? __ldcg(A4 + tid) : A4[tid];
            }
            wv = *(const float4*)(Wp + (size_t)wkr * ldw + wku);
        }
        {   // store chunk c0 -> buffer 0
            if (tid < 256) ((float4*)AsB[0])[tid] = av;
            *(float4*)&WsB[0][wkr * TILEN + wku] = wv;
        }

        int p = 0;
        for (int c = c0; c < c1; ++c) {
            const int gtile = tile_of(c);
            if (gtile != cur_tile) {
                if (cur_tile >= 0) {   // flush old tile's partials (coalesced)
                    const int fc = tile_first_chunk(cur_tile);
                    float* base = g_part[bid - fc / CPB]
                                + ((size_t)cur_tile * TILEN + o0) * BB + b0;
                    #pragma unroll
                    for (int j = 0; j < 4; j++)
                        *(float4*)(base + j * BB) = acc[j];
                }
                #pragma unroll
                for (int j = 0; j < 4; j++)
                    acc[j] = make_float4(0.f, 0.f, 0.f, 0.f);
                cur_tile = gtile;
            }

            __syncthreads();   // buf p stores visible; prior reads of p^1 done

            if (c + 1 < c1) {  // prefetch next chunk into regs
                const float *Ap, *Wp; size_t ldw; bool cg;
                chunk_ptrs(c + 1, t, cur, Ap, Wp, ldw, cg);
                if (tid < 256) {
                    const float4* A4 = (const float4*)Ap;
                    av = cg ? __ldcg(A4 + tid) : A4[tid];
                }
                wv = *(const float4*)(Wp + (size_t)wkr * ldw + wku);
            }

            // compute on buffer p: per k, 2 LDS.128 + 16 FFMA
            {
                const float* Ar = AsB[p];
                const float* Wr = WsB[p];
                #pragma unroll
                for (int k = 0; k < TK; ++k) {
                    float4 a = *(const float4*)(Ar + k * 64 + b0);
                    float4 w = *(const float4*)(Wr + k * TILEN + o0);
                    acc[0].x += a.x * w.x; acc[0].y += a.y * w.x;
                    acc[0].z += a.z * w.x; acc[0].w += a.w * w.x;
                    acc[1].x += a.x * w.y; acc[1].y += a.y * w.y;
                    acc[1].z += a.z * w.y; acc[1].w += a.w * w.y;
                    acc[2].x += a.x * w.z; acc[2].y += a.y * w.z;
                    acc[2].z += a.z * w.z; acc[2].w += a.w * w.z;
                    acc[3].x += a.x * w.w; acc[3].y += a.y * w.w;
                    acc[3].z += a.z * w.w; acc[3].w += a.w * w.w;
                }
            }

            if (c + 1 < c1) {  // store prefetched chunk -> buffer p^1
                const int q = p ^ 1;
                if (tid < 256) ((float4*)AsB[q])[tid] = av;
                *(float4*)&WsB[q][wkr * TILEN + wku] = wv;
            }
            p ^= 1;
        }
        {   // final flush
            const int fc = tile_first_chunk(cur_tile);
            float* base = g_part[bid - fc / CPB]
                        + ((size_t)cur_tile * TILEN + o0) * BB + b0;
            #pragma unroll
            for (int j = 0; j < 4; j++)
                *(float4*)(base + j * BB) = acc[j];
        }

        // ---- P1b: surprisal dot -> gate (previous step's xp & lse) ----
        // 512 jobs (b,m); each block does 4, two at a time (tid>>8 picks job).
        #pragma unroll
        for (int it = 0; it < 2; ++it) {
            const int d = bid + (it * 2 + (tid >> 8)) * NB;  // 0..511
            const int b = d >> 3, m = d & 7;
            const int i = tid & 255;
            float xv  = x[((size_t)b * TT + t) * II + i];
            float xpv = __ldcg(&g_xp[cur][(size_t)(m * II + i) * BB + b]);
            float lsv = __ldcg(&g_lse[cur][m * II + i]);
            float part = (xpv - lsv) * xv;
            #pragma unroll
            for (int off = 16; off; off >>= 1)
                part += __shfl_xor_sync(0xffffffffu, part, off);
            __syncthreads();
            if ((tid & 31) == 0) red[tid >> 5] = part;
            __syncthreads();
            if ((tid & 255) == 0) {
                const int g8 = (tid >> 8) * 8;
                float tot = 0.f;
                #pragma unroll
                for (int w = 0; w < 8; w++) tot += red[g8 + w];
                float mp = tot * (1.0f / II) * periods[m];
                float gate = (sinf((float)t * mp + shifts[m]) + 1.f) * 0.5f;
                g_gate[d] = gate;
                ps[((size_t)b * TT + t) * MM + m] = mp;
            }
        }

        gbar(gen++);

        // ============ P2: reduce + activate + blend + fused LSE ============
        {
            float* redm = &AsB[0][0];
            float* reds = &AsB[0][16];
            const int c0p = bid * 24;
            const int bb  = tid & 63;
            const int clq = tid >> 6;     // 0..7
            const int w   = tid >> 5;     // 0..15
            #pragma unroll
            for (int pass = 0; pass < 3; ++pass) {
                const int col  = c0p + pass * 8 + clq;
                const int tile = col >> 7;
                const int fc    = tile_first_chunk(tile);
                const int lastc = fc + ((tile < RECTILES) ? RECCPT - 1 : ACTCPT - 1);
                const int ns    = lastc / CPB - fc / CPB;    // slots-1
                float s = 0.f;
                for (int sl = 0; sl <= ns; ++sl)
                    s += __ldcg(&g_part[sl][(size_t)col * BB + bb]);
                const bool isrec = col < IMD;
                float v = 0.f;
                if (isrec) {
                    v = tanhf(s + b_ir[col]);
                    g_xp[nxt][(size_t)col * BB + bb] = v;
                } else {
                    const int o = col - IMD;
                    float a  = tanhf(s + b_in[o]);
                    float gt = __ldcg(&g_gate[bb * MM + (o >> 7)]);
                    float hv = g_hT[(size_t)o * BB + bb];
                    float y  = (1.f - gt) * a + gt * hv;
                    g_hT[(size_t)o * BB + bb] = y;
                    ys[((size_t)bb * TT + t) * OO + o] = y;
                }
                // column LSE over 64 batches (2 warps); act cols -> junk, unused
                float mx = v;
                #pragma unroll
                for (int off = 16; off; off >>= 1)
                    mx = fmaxf(mx, __shfl_xor_sync(0xffffffffu, mx, off));
                float se = isrec ? expf(v - mx) : 0.f;
                #pragma unroll
                for (int off = 16; off; off >>= 1)
                    se += __shfl_xor_sync(0xffffffffu, se, off);
                __syncthreads();
                if ((tid & 31) == 0) { redm[w] = mx; reds[w] = se; }
                __syncthreads();
                if (isrec && (tid & 63) == 0) {
                    float m0 = redm[w], m1 = redm[w + 1];
                    float M = fmaxf(m0, m1);
                    float S = reds[w] * expf(m0 - M) + reds[w + 1] * expf(m1 - M);
                    g_lse[nxt][col] = M + logf(S);
                }
            }
        }

        gbar(gen++);
    }

    // h_final: col-major -> [B][O]  (NB*NTH == BB*OO exactly)
    {
        int idx = bid * NTH + tid;
        int o = idx >> 6, b = idx & 63;
        hfin[(size_t)b * OO + o] = __ldcg(&g_hT[idx]);
    }
}

// ---------------------------------------------------------------------------
// 2 graph nodes. Inputs: x, W_in, b_in, W_h, W_ir, b_ir, W_hr, periods, shifts
// Output: concat(ys [B,T,O], h_final [B,O], ps [B,T,M]) fp32
// ---------------------------------------------------------------------------
extern "C" void kernel_launch(void* const* d_in, const int* in_sizes, int n_in,
                              void* d_out, int out_size) {
    const float* x       = (const float*)d_in[0];
    const float* W_in    = (const float*)d_in[1];
    const float* b_in    = (const float*)d_in[2];
    const float* W_h     = (const float*)d_in[3];
    const float* W_ir    = (const float*)d_in[4];
    const float* b_ir    = (const float*)d_in[5];
    const float* W_hr    = (const float*)d_in[6];
    const float* periods = (const float*)d_in[7];
    const float* shifts  = (const float*)d_in[8];

    float* out  = (float*)d_out;
    float* ys   = out;                                  // [B,T,O]
    float* hfin = out + (size_t)BB * TT * OO;           // [B,O]
    float* ps   = hfin + (size_t)BB * OO;               // [B,T,M]

    init_kernel<<<1024, 256>>>(x, W_in, W_h, W_ir, W_hr);
    rnn_persistent<<<NB, NTH>>>(x, b_in, b_ir, periods, shifts, ys, hfin, ps);
}

// round 11
// speedup vs baseline: 2.2228x; 1.1478x over previous
#include <cuda_runtime.h>
#include <math.h>

// Problem constants
#define BB  64
#define TT  512
#define II  256
#define OO  1024
#define MM  8
#define IMD 2048

// Persistent-kernel configuration
#define NB   128            // persistent blocks (co-resident: 128 <= SM count)
#define NTH  512
#define TK   8              // K-chunk depth
#define TILEN 256           // output-cols per tile
#define ARPAD 68            // padded A smem row (floats), swizzle-friendly
#define NSLOT 12            // split-K ways: rec 12, act 8

// ---------------------------------------------------------------------------
// Device state (allocation-free).  Column-major activations: [col][batch].
// ---------------------------------------------------------------------------
__device__ float g_xT[(size_t)TT * II * BB];   // x transposed: [t][i][b]
__device__ float g_WinT[(size_t)II * OO];      // W_in^T  [k][n]
__device__ float g_WhT [(size_t)OO * OO];      // W_h^T   [k][n]
__device__ float g_WirT[(size_t)II * IMD];     // W_ir^T  [k][n]
__device__ float g_WhrT[(size_t)IMD * IMD];    // W_hr^T  [k][n]
__device__ float g_xp[2][(size_t)IMD * BB];    // x_pred col-major, ping-pong
__device__ float g_hT[(size_t)OO * BB];        // hidden col-major
__device__ float g_lse[2][IMD];                // batch-axis logsumexp
__device__ float g_gate[BB * MM];
__device__ float g_part[NSLOT][(size_t)(IMD + OO) * BB]; // partials [col][b]
__device__ unsigned g_arrive;
__device__ volatile unsigned g_release;

// ---------------------------------------------------------------------------
__global__ void init_kernel(const float* __restrict__ x,
                            const float* __restrict__ W_in,
                            const float* __restrict__ W_h,
                            const float* __restrict__ W_ir,
                            const float* __restrict__ W_hr) {
    size_t i = (size_t)blockIdx.x * blockDim.x + threadIdx.x;
    size_t n = (size_t)gridDim.x * blockDim.x;
    for (size_t j = i; j < (size_t)TT * II * BB; j += n) {
        size_t b = j & 63, ti = j >> 6;
        size_t ii = ti % II, tt = ti / II;
        g_xT[j] = x[(b * TT + tt) * II + ii];
    }
    for (size_t j = i; j < (size_t)II * OO; j += n) {
        size_t nn = j % OO, k = j / OO;
        g_WinT[j] = W_in[nn * II + k];
    }
    for (size_t j = i; j < (size_t)OO * OO; j += n) {
        size_t nn = j % OO, k = j / OO;
        g_WhT[j] = W_h[nn * OO + k];
    }
    for (size_t j = i; j < (size_t)II * IMD; j += n) {
        size_t nn = j % IMD, k = j / IMD;
        g_WirT[j] = W_ir[nn * II + k];
    }
    for (size_t j = i; j < (size_t)IMD * IMD; j += n) {
        size_t nn = j % IMD, k = j / IMD;
        g_WhrT[j] = W_hr[nn * IMD + k];
    }
    for (size_t j = i; j < (size_t)IMD * BB; j += n) g_xp[0][j] = 0.f;
    for (size_t j = i; j < (size_t)OO * BB;  j += n) g_hT[j] = 0.f;
    for (size_t j = i; j < IMD; j += n) g_lse[0][j] = logf((float)BB);
    if (i == 0) { g_arrive = 0u; g_release = 0u; }
}

// Grid-wide barrier (all NB blocks resident by construction)
__device__ __forceinline__ void gbar(unsigned gen) {
    __syncthreads();
    if (threadIdx.x == 0) {
        __threadfence();
        unsigned v = atomicAdd(&g_arrive, 1u);
        if (v == gen * NB + (NB - 1u)) {
            g_release = gen + 1u;
        } else {
            while (g_release <= gen) { __nanosleep(64); }
        }
    }
    __syncthreads();
}

// ---------------------------------------------------------------------------
// Whole scan, one kernel. Per step: P1 GEMM(+gate) | bar | P2 reduce+act+LSE | bar
// ---------------------------------------------------------------------------
__global__ void __launch_bounds__(NTH) rnn_persistent(
    const float* __restrict__ x,
    const float* __restrict__ b_in, const float* __restrict__ b_ir,
    const float* __restrict__ periods, const float* __restrict__ shifts,
    float* __restrict__ ys, float* __restrict__ hfin, float* __restrict__ ps)
{
    __shared__ float AsB[2][TK * ARPAD];     // swizzled A tiles [k][68]
    __shared__ float WsB[2][TK * TILEN];     // k-major W tiles  [k][256]
    float* red = &AsB[0][0];                 // scratch alias (reductions)

    const int tid = threadIdx.x;
    const int bid = blockIdx.x;

    // Per-block static tile assignment (no runtime divisions in the hot loop)
    const bool recb = (bid < 96);
    const int tile  = recb ? (bid / 12) : ((bid - 96) / 8);
    const int slot  = recb ? (bid % 12) : ((bid - 96) % 8);
    const int koff  = slot * (recb ? 192 : 160);
    const int nch   = recb ? 24 : 20;                 // chunks of TK=8
    const int n0    = tile * TILEN;                   // col offset within W
    const int col0  = recb ? n0 : (IMD + n0);         // global partial col
    const float* W1 = recb ? g_WirT : g_WinT;         // k <  II source
    const float* W2 = recb ? g_WhrT : g_WhT;          // k >= II source
    const int ldw   = recb ? IMD : OO;

    // GEMM thread tile: 8 batches x 4 outputs
    const int g   = tid & 7;                  // batch group
    const int b0  = g * 8;                    // batches b0..b0+7
    const int boff = g * 8 + (g >> 2) * 4;    // swizzled smem float offset
    const int o0  = (tid >> 3) * 4;           // outputs o0..o0+3 (0..252)
    // Loader indices
    const int ak  = tid >> 4, ac = tid & 15;                // A: k, 16B-chunk
    const int adst = ak * 17 + ac + (ac >> 3);              // swizzled f4 idx
    const int wrow = tid >> 6;                              // W: k row (0..7)
    const int wcol = (tid & 63) * 4;                        // float offset

    unsigned gen = 0;
    for (int t = 0; t < TT; t++) {
        const int cur = t & 1, nxt = cur ^ 1;

        // ================= P1: one 64x256 tile, K-slice [koff, koff+nch*8) ==
        float4 acc[4][2];
        #pragma unroll
        for (int j = 0; j < 4; j++) {
            acc[j][0] = make_float4(0.f, 0.f, 0.f, 0.f);
            acc[j][1] = make_float4(0.f, 0.f, 0.f, 0.f);
        }

        float4 av, wv;
        {   // preload chunk 0
            const int k0 = koff;
            const float* Ap; const float* Wp; bool cg;
            if (k0 < II) { Ap = g_xT + ((size_t)t * II + k0) * BB;
                           Wp = W1 + (size_t)k0 * ldw + n0; cg = false; }
            else { const int kk = k0 - II;
                   Ap = (recb ? g_xp[cur] : g_hT) + (size_t)kk * BB;
                   Wp = W2 + (size_t)kk * ldw + n0; cg = true; }
            if (tid < 128) {
                const float4* A4 = (const float4*)Ap;
                av = cg ? __ldcg(A4 + tid) : A4[tid];
            }
            wv = *(const float4*)(Wp + (size_t)wrow * ldw + wcol);
        }
        {   // store chunk 0 -> buffer 0
            if (tid < 128) ((float4*)AsB[0])[adst] = av;
            ((float4*)WsB[0])[tid] = wv;
        }

        int p = 0;
        for (int c = 0; c < nch; ++c) {
            __syncthreads();   // buf p stores visible; prior reads of p^1 done

            if (c + 1 < nch) {  // prefetch next chunk into regs
                const int k0 = koff + (c + 1) * TK;
                const float* Ap; const float* Wp; bool cg;
                if (k0 < II) { Ap = g_xT + ((size_t)t * II + k0) * BB;
                               Wp = W1 + (size_t)k0 * ldw + n0; cg = false; }
                else { const int kk = k0 - II;
                       Ap = (recb ? g_xp[cur] : g_hT) + (size_t)kk * BB;
                       Wp = W2 + (size_t)kk * ldw + n0; cg = true; }
                if (tid < 128) {
                    const float4* A4 = (const float4*)Ap;
                    av = cg ? __ldcg(A4 + tid) : A4[tid];
                }
                wv = *(const float4*)(Wp + (size_t)wrow * ldw + wcol);
            }

            // compute on buffer p: per k, 3 LDS.128 + 32 FFMA
            {
                const float* Ar = AsB[p];
                const float* Wr = WsB[p];
                #pragma unroll
                for (int k = 0; k < TK; ++k) {
                    float4 a0 = *(const float4*)(Ar + k * ARPAD + boff);
                    float4 a1 = *(const float4*)(Ar + k * ARPAD + boff + 4);
                    float4 w  = *(const float4*)(Wr + k * TILEN + o0);
                    acc[0][0].x += a0.x * w.x; acc[0][0].y += a0.y * w.x;
                    acc[0][0].z += a0.z * w.x; acc[0][0].w += a0.w * w.x;
                    acc[0][1].x += a1.x * w.x; acc[0][1].y += a1.y * w.x;
                    acc[0][1].z += a1.z * w.x; acc[0][1].w += a1.w * w.x;
                    acc[1][0].x += a0.x * w.y; acc[1][0].y += a0.y * w.y;
                    acc[1][0].z += a0.z * w.y; acc[1][0].w += a0.w * w.y;
                    acc[1][1].x += a1.x * w.y; acc[1][1].y += a1.y * w.y;
                    acc[1][1].z += a1.z * w.y; acc[1][1].w += a1.w * w.y;
                    acc[2][0].x += a0.x * w.z; acc[2][0].y += a0.y * w.z;
                    acc[2][0].z += a0.z * w.z; acc[2][0].w += a0.w * w.z;
                    acc[2][1].x += a1.x * w.z; acc[2][1].y += a1.y * w.z;
                    acc[2][1].z += a1.z * w.z; acc[2][1].w += a1.w * w.z;
                    acc[3][0].x += a0.x * w.w; acc[3][0].y += a0.y * w.w;
                    acc[3][0].z += a0.z * w.w; acc[3][0].w += a0.w * w.w;
                    acc[3][1].x += a1.x * w.w; acc[3][1].y += a1.y * w.w;
                    acc[3][1].z += a1.z * w.w; acc[3][1].w += a1.w * w.w;
                }
            }

            if (c + 1 < nch) {  // store prefetched chunk -> buffer p^1
                const int q = p ^ 1;
                if (tid < 128) ((float4*)AsB[q])[adst] = av;
                ((float4*)WsB[q])[tid] = wv;
            }
            p ^= 1;
        }
        {   // flush partials (single tile per block)
            float* base = g_part[slot] + ((size_t)(col0 + o0)) * BB + b0;
            #pragma unroll
            for (int j = 0; j < 4; j++) {
                *(float4*)(base + (size_t)j * BB)     = acc[j][0];
                *(float4*)(base + (size_t)j * BB + 4) = acc[j][1];
            }
        }

        // ---- P1b: surprisal dot -> gate (previous step's xp & lse) ----
        // 512 jobs (b,m); each block does 4, two at a time (tid>>8 picks job).
        #pragma unroll
        for (int it = 0; it < 2; ++it) {
            const int d = bid + (it * 2 + (tid >> 8)) * NB;  // 0..511
            const int b = d >> 3, m = d & 7;
            const int i = tid & 255;
            float xv  = x[((size_t)b * TT + t) * II + i];
            float xpv = __ldcg(&g_xp[cur][(size_t)(m * II + i) * BB + b]);
            float lsv = __ldcg(&g_lse[cur][m * II + i]);
            float part = (xpv - lsv) * xv;
            #pragma unroll
            for (int off = 16; off; off >>= 1)
                part += __shfl_xor_sync(0xffffffffu, part, off);
            __syncthreads();
            if ((tid & 31) == 0) red[tid >> 5] = part;
            __syncthreads();
            if ((tid & 255) == 0) {
                const int g8 = (tid >> 8) * 8;
                float tot = 0.f;
                #pragma unroll
                for (int w = 0; w < 8; w++) tot += red[g8 + w];
                float mp = tot * (1.0f / II) * periods[m];
                float gate = (sinf((float)t * mp + shifts[m]) + 1.f) * 0.5f;
                g_gate[d] = gate;
                ps[((size_t)b * TT + t) * MM + m] = mp;
            }
        }

        gbar(gen++);

        // ============ P2: reduce + activate + blend + fused LSE ============
        {
            float* redm = &AsB[0][0];
            float* reds = &AsB[0][16];
            const int c0p = bid * 24;
            const int bb  = tid & 63;
            const int clq = tid >> 6;     // 0..7
            const int w   = tid >> 5;     // 0..15
            #pragma unroll
            for (int pass = 0; pass < 3; ++pass) {
                const int col = c0p + pass * 8 + clq;
                const bool isrec = col < IMD;
                const int nslots = isrec ? 12 : 8;
                float s = 0.f;
                for (int sl = 0; sl < nslots; ++sl)
                    s += __ldcg(&g_part[sl][(size_t)col * BB + bb]);
                float v = 0.f;
                if (isrec) {
                    v = tanhf(s + b_ir[col]);
                    g_xp[nxt][(size_t)col * BB + bb] = v;
                } else {
                    const int o = col - IMD;
                    float a  = tanhf(s + b_in[o]);
                    float gt = __ldcg(&g_gate[bb * MM + (o >> 7)]);
                    float hv = g_hT[(size_t)o * BB + bb];
                    float y  = (1.f - gt) * a + gt * hv;
                    g_hT[(size_t)o * BB + bb] = y;
                    ys[((size_t)bb * TT + t) * OO + o] = y;
                }
                // column LSE over 64 batches (2 warps); act cols -> junk, unused
                float mx = v;
                #pragma unroll
                for (int off = 16; off; off >>= 1)
                    mx = fmaxf(mx, __shfl_xor_sync(0xffffffffu, mx, off));
                float se = isrec ? expf(v - mx) : 0.f;
                #pragma unroll
                for (int off = 16; off; off >>= 1)
                    se += __shfl_xor_sync(0xffffffffu, se, off);
                __syncthreads();
                if ((tid & 31) == 0) { redm[w] = mx; reds[w] = se; }
                __syncthreads();
                if (isrec && (tid & 63) == 0) {
                    float m0 = redm[w], m1 = redm[w + 1];
                    float M = fmaxf(m0, m1);
                    float S = reds[w] * expf(m0 - M) + reds[w + 1] * expf(m1 - M);
                    g_lse[nxt][col] = M + logf(S);
                }
            }
        }

        gbar(gen++);
    }

    // h_final: col-major -> [B][O]  (NB*NTH == BB*OO exactly)
    {
        int idx = bid * NTH + tid;
        int o = idx >> 6, b = idx & 63;
        hfin[(size_t)b * OO + o] = __ldcg(&g_hT[idx]);
    }
}

// ---------------------------------------------------------------------------
// 2 graph nodes. Inputs: x, W_in, b_in, W_h, W_ir, b_ir, W_hr, periods, shifts
// Output: concat(ys [B,T,O], h_final [B,O], ps [B,T,M]) fp32
// ---------------------------------------------------------------------------
extern "C" void kernel_launch(void* const* d_in, const int* in_sizes, int n_in,
                              void* d_out, int out_size) {
    const float* x       = (const float*)d_in[0];
    const float* W_in    = (const float*)d_in[1];
    const float* b_in    = (const float*)d_in[2];
    const float* W_h     = (const float*)d_in[3];
    const float* W_ir    = (const float*)d_in[4];
    const float* b_ir    = (const float*)d_in[5];
    const float* W_hr    = (const float*)d_in[6];
    const float* periods = (const float*)d_in[7];
    const float* shifts  = (const float*)d_in[8];

    float* out  = (float*)d_out;
    float* ys   = out;                                  // [B,T,O]
    float* hfin = out + (size_t)BB * TT * OO;           // [B,O]
    float* ps   = hfin + (size_t)BB * OO;               // [B,T,M]

    init_kernel<<<1024, 256>>>(x, W_in, W_h, W_ir, W_hr);
    rnn_persistent<<<NB, NTH>>>(x, b_in, b_ir, periods, shifts, ys, hfin, ps);
}